// round 13
// baseline (speedup 1.0000x reference)
#include <cuda_runtime.h>
#include <cuda_bf16.h>
#include <cstdint>

#define Bz 32
#define Tz 4096
#define DECz 1024
#define ENCz 1024
#define ATTNz 512
#define Kz 10

// ---------------- device scratch (no allocation allowed) ----------------
__device__ __nv_bfloat16 g_valh[(size_t)Bz * Tz * ENCz];  // 256 MB bf16 value
__device__ __nv_bfloat16 g_WVh[ATTNz * ENCz];             // bf16 WV, K-major
__device__ float g_qpb[Bz * ATTNz];                       // q·WQ^T + bias + cb
__device__ float g_cu0[ATTNz], g_cu1[ATTNz], g_cu2[ATTNz];
__device__ float g_ps[1024 * 4 * 128];                    // [mtile][nchunk][row]
__device__ float g_sN[Bz * Tz];
__device__ float g_pctx[Bz * 32 * ENCz];

// ---------------- PTX helpers ----------------
__device__ __forceinline__ uint32_t smem_u32(const void* p) {
    uint32_t a;
    asm("{ .reg .u64 t; cvta.to.shared.u64 t, %1; cvt.u32.u64 %0, t; }" : "=r"(a) : "l"(p));
    return a;
}
__device__ __forceinline__ void cpasync16(uint32_t sdst, const void* gsrc) {
    asm volatile("cp.async.cg.shared.global [%0], [%1], 16;\n" ::"r"(sdst), "l"(gsrc));
}
#define CP_COMMIT() asm volatile("cp.async.commit_group;\n")
template <int N>
__device__ __forceinline__ void cp_wait() {
    asm volatile("cp.async.wait_group %0;\n" ::"n"(N) : "memory");
}
__device__ __forceinline__ void ldsm4(uint32_t& r0, uint32_t& r1, uint32_t& r2,
                                      uint32_t& r3, uint32_t addr) {
    asm volatile("ldmatrix.sync.aligned.m8n8.x4.shared.b16 {%0,%1,%2,%3}, [%4];"
                 : "=r"(r0), "=r"(r1), "=r"(r2), "=r"(r3)
                 : "r"(addr));
}
__device__ __forceinline__ void mma16816(float c[4], const uint32_t a[4],
                                         uint32_t b0, uint32_t b1) {
    asm volatile(
        "mma.sync.aligned.m16n8k16.row.col.f32.bf16.bf16.f32 "
        "{%0,%1,%2,%3}, {%4,%5,%6,%7}, {%8,%9}, {%0,%1,%2,%3};\n"
        : "+f"(c[0]), "+f"(c[1]), "+f"(c[2]), "+f"(c[3])
        : "r"(a[0]), "r"(a[1]), "r"(a[2]), "r"(a[3]), "r"(b0), "r"(b1));
}
__device__ __forceinline__ float tanh_fast(float x) {
    float y;
    asm("tanh.approx.f32 %0, %1;" : "=f"(y) : "f"(x));
    return y;
}
__device__ __forceinline__ uint32_t swz(uint32_t off) {
    return off ^ ((off >> 3) & 0x70);
}

// ---------------- prep kernels (separate launches — fusion cost +14.5us) --
// 64 B per thread: 4x LDG.128 -> 4x STG.128 (converted)
__global__ void k_prep_val(const float4* __restrict__ V4) {
    size_t base = ((size_t)blockIdx.x * blockDim.x + threadIdx.x) * 4;  // uint4 idx
    uint4* dst = reinterpret_cast<uint4*>(g_valh);
#pragma unroll
    for (int u = 0; u < 4; u++) {
        size_t i = base + u;
        float4 v0 = V4[2 * i], v1 = V4[2 * i + 1];
        __nv_bfloat162 h0 = __floats2bfloat162_rn(v0.x, v0.y);
        __nv_bfloat162 h1 = __floats2bfloat162_rn(v0.z, v0.w);
        __nv_bfloat162 h2 = __floats2bfloat162_rn(v1.x, v1.y);
        __nv_bfloat162 h3 = __floats2bfloat162_rn(v1.z, v1.w);
        uint4 o;
        o.x = reinterpret_cast<uint32_t&>(h0);
        o.y = reinterpret_cast<uint32_t&>(h1);
        o.z = reinterpret_cast<uint32_t&>(h2);
        o.w = reinterpret_cast<uint32_t&>(h3);
        dst[i] = o;
    }
}

__global__ void k_prep_wv(const float4* __restrict__ WV4) {
    int i = blockIdx.x * blockDim.x + threadIdx.x;
    float4 v = WV4[i];
    __nv_bfloat162 p0 = __floats2bfloat162_rn(v.x, v.y);
    __nv_bfloat162 p1 = __floats2bfloat162_rn(v.z, v.w);
    __nv_bfloat162* dst = reinterpret_cast<__nv_bfloat162*>(g_WVh);
    dst[2 * i + 0] = p0;
    dst[2 * i + 1] = p1;
}

// qpb (blocks 0..2047; includes bias + conv-bias fold) + cu tables (block 2048)
__global__ void k_qpb_cu(const float* __restrict__ q, const float* __restrict__ WQ,
                         const float* __restrict__ bias, const float* __restrict__ WU,
                         const float* __restrict__ cw, const float* __restrict__ cbv) {
    if (blockIdx.x == 2048) {
        for (int a = threadIdx.x; a < ATTNz; a += 256) {
            float s0 = 0.f, s1 = 0.f, s2 = 0.f;
#pragma unroll
            for (int k = 0; k < Kz; k++) {
                float w = WU[a * Kz + k];
                s0 += w * cw[k * 3 + 0];
                s1 += w * cw[k * 3 + 1];
                s2 += w * cw[k * 3 + 2];
            }
            g_cu0[a] = s0; g_cu1[a] = s1; g_cu2[a] = s2;
        }
        return;
    }
    int w = (blockIdx.x * blockDim.x + threadIdx.x) >> 5;
    int lane = threadIdx.x & 31;
    int b = w >> 9, a = w & 511;
    const float* qr = q + (size_t)b * DECz;
    const float* wr = WQ + (size_t)a * DECz;
    float s = 0.f;
    for (int d = lane; d < DECz; d += 32) s += qr[d] * wr[d];
#pragma unroll
    for (int o = 16; o; o >>= 1) s += __shfl_xor_sync(0xffffffffu, s, o);
    if (lane == 0) {
        float cb = 0.f;
#pragma unroll
        for (int k = 0; k < Kz; k++) cb += WU[a * Kz + k] * cbv[k];
        g_qpb[b * ATTNz + a] = s + bias[a] + cb;
    }
}

// ---------------- GEMM: 128x128 CTA tile, K=1024 in 16 chunks of 64 -------
// 3-stage cp.async pipeline, ldmatrix operands double-buffered across the 4
// k-steps of each chunk, 8 warps 4(M)x2(N), warp 32x64.  (R10 config — best;
// epilogue is register-allocation-fragile: do NOT restructure it.)
#define STAGE_A 16384
#define STAGE_B 16384
#define STAGE_BYTES 32768
#define OFF_SCORE (3 * STAGE_BYTES)
#define SMEM_TOTAL (3 * STAGE_BYTES + 1024)

__global__ __launch_bounds__(256, 2) void k_gemm(const float* __restrict__ la,
                                                 const float* __restrict__ fcw) {
    extern __shared__ char smem[];
    const uint32_t sbase = smem_u32(smem);
    const int tid = threadIdx.x, warp = tid >> 5, lane = tid & 31;
    const int nchunk = blockIdx.x;   // 0..3
    const int mtile = blockIdx.y;    // 0..1023
    const int wm = warp & 3, wn = warp >> 2;
    const int b = mtile >> 5;
    const int tt0 = (mtile & 31) << 7;
    const int g = lane >> 2, t4 = lane & 3;

    const char* Ag = reinterpret_cast<const char*>(g_valh) + (size_t)mtile * 128 * 2048;
    const char* Bg = reinterpret_cast<const char*>(g_WVh) + (size_t)nchunk * 128 * 2048;

    const int lr = tid >> 3, lseg = tid & 7;

    auto load_stage = [&](int c) {
        uint32_t dA = sbase + (c % 3) * STAGE_BYTES;
        uint32_t dB = dA + STAGE_A;
        const char* As = Ag + (size_t)lr * 2048 + c * 128 + lseg * 16;
        const char* Bs = Bg + (size_t)lr * 2048 + c * 128 + lseg * 16;
#pragma unroll
        for (int p = 0; p < 4; p++) {
            uint32_t off = swz((lr + 32 * p) * 128 + lseg * 16);
            cpasync16(dA + off, As + (size_t)(32 * p) * 2048);
            cpasync16(dB + off, Bs + (size_t)(32 * p) * 2048);
        }
        CP_COMMIT();
    };

    // ldmatrix per-lane base offsets (stage-relative); k-step advance is XOR
    // (swz(x + ks*32) == swz(x) ^ (ks*32) since pre-swizzle bits [5:6] are 0).
    const int lrow = lane & 15, lk = lane >> 4;
    uint32_t aoff[2], boff[4];
#pragma unroll
    for (int mt = 0; mt < 2; mt++)
        aoff[mt] = swz((wm * 32 + mt * 16 + lrow) * 128 + lk * 16);
#pragma unroll
    for (int nb = 0; nb < 4; nb++)
        boff[nb] = swz((wn * 64 + nb * 16 + lrow) * 128 + lk * 16);

    float acc[2][8][4];
#pragma unroll
    for (int mt = 0; mt < 2; mt++)
#pragma unroll
        for (int nt = 0; nt < 8; nt++)
#pragma unroll
            for (int j = 0; j < 4; j++) acc[mt][nt][j] = 0.f;

    load_stage(0);
    load_stage(1);

    for (int c = 0; c < 16; c++) {
        if (c < 15) cp_wait<1>(); else cp_wait<0>();
        __syncthreads();
        if (c + 2 < 16) load_stage(c + 2);

        uint32_t stA = sbase + (c % 3) * STAGE_BYTES;
        uint32_t stB = stA + STAGE_A;

        // fragment double buffers across k-steps
        uint32_t af[2][2][4];
        uint32_t qf[2][4][4];
        ldsm4(af[0][0][0], af[0][0][1], af[0][0][2], af[0][0][3], stA + aoff[0]);
        ldsm4(af[0][1][0], af[0][1][1], af[0][1][2], af[0][1][3], stA + aoff[1]);
#pragma unroll
        for (int nb = 0; nb < 4; nb++)
            ldsm4(qf[0][nb][0], qf[0][nb][1], qf[0][nb][2], qf[0][nb][3],
                  stB + boff[nb]);
#pragma unroll
        for (int ks = 0; ks < 4; ks++) {
            const int cur = ks & 1, nxt = cur ^ 1;
            if (ks < 3) {
                const uint32_t kx = (ks + 1) * 32;
                ldsm4(af[nxt][0][0], af[nxt][0][1], af[nxt][0][2], af[nxt][0][3],
                      stA + (aoff[0] ^ kx));
                ldsm4(af[nxt][1][0], af[nxt][1][1], af[nxt][1][2], af[nxt][1][3],
                      stA + (aoff[1] ^ kx));
#pragma unroll
                for (int nb = 0; nb < 4; nb++)
                    ldsm4(qf[nxt][nb][0], qf[nxt][nb][1], qf[nxt][nb][2],
                          qf[nxt][nb][3], stB + (boff[nb] ^ kx));
            }
#pragma unroll
            for (int nb = 0; nb < 4; nb++) {
#pragma unroll
                for (int mt = 0; mt < 2; mt++) {
                    mma16816(acc[mt][2 * nb + 0], af[cur][mt], qf[cur][nb][0],
                             qf[cur][nb][2]);
                    mma16816(acc[mt][2 * nb + 1], af[cur][mt], qf[cur][nb][1],
                             qf[cur][nb][3]);
                }
            }
        }
    }

    // -------- epilogue: tanh + fc_w dot, partial over this nchunk --------
    // (exact R10 form — register-allocation-fragile, do not restructure)
    const float* lab = la + (size_t)b * Tz;
    float lm[4], l0[4], lp[4];
#pragma unroll
    for (int i = 0; i < 4; i++) {
        int r = 32 * wm + 16 * (i >> 1) + g + 8 * (i & 1);
        int t = tt0 + r;
        l0[i] = lab[t];
        lm[i] = (t > 0) ? lab[t - 1] : 0.f;
        lp[i] = (t < Tz - 1) ? lab[t + 1] : 0.f;
    }
    float rsum[4] = {0.f, 0.f, 0.f, 0.f};
#pragma unroll
    for (int mt = 0; mt < 2; mt++) {
#pragma unroll
        for (int nt = 0; nt < 8; nt++) {
#pragma unroll
            for (int j = 0; j < 4; j++) {
                int ridx = (mt << 1) | (j >> 1);
                int col = 64 * wn + 8 * nt + 2 * t4 + (j & 1);
                int a = (nchunk << 7) + col;
                float x = acc[mt][nt][j] + g_qpb[(b << 9) + a] +
                          g_cu0[a] * lm[ridx] + g_cu1[a] * l0[ridx] +
                          g_cu2[a] * lp[ridx];
                rsum[ridx] += fcw[a] * tanh_fast(x);
            }
        }
    }
    __syncthreads();
    float* scoreSm = reinterpret_cast<float*>(smem + OFF_SCORE);
#pragma unroll
    for (int i = 0; i < 4; i++) {
        float v = rsum[i];
        v += __shfl_xor_sync(0xffffffffu, v, 1);
        v += __shfl_xor_sync(0xffffffffu, v, 2);
        if (t4 == 0) {
            int r = 32 * wm + 16 * (i >> 1) + g + 8 * (i & 1);
            scoreSm[r * 2 + wn] = v;
        }
    }
    __syncthreads();
    if (tid < 128) {
        g_ps[((size_t)(mtile * 4 + nchunk)) * 128 + tid] =
            scoreSm[tid * 2 + 0] + scoreSm[tid * 2 + 1];
    }
}

// ---------------- sigmoid + normalize (deterministic) ----------------
__global__ void k_score(float* align_out) {
    int b = blockIdx.x, tid = threadIdx.x;
    __shared__ float red[256];
    float lsum = 0.f;
    for (int i = tid; i < Tz; i += 256) {
        int mtile = (b << 5) + (i >> 7);
        int r = i & 127;
        const float* p = g_ps + (size_t)mtile * 4 * 128 + r;
        float sraw = p[0] + p[128] + p[256] + p[384];
        float s = 1.f / (1.f + __expf(-sraw));
        g_sN[(b << 12) + i] = s;
        lsum += s;
    }
    red[tid] = lsum;
    __syncthreads();
#pragma unroll
    for (int o = 128; o; o >>= 1) {
        if (tid < o) red[tid] += red[tid + o];
        __syncthreads();
    }
    float inv = 1.f / red[0];
    for (int i = tid; i < Tz; i += 256) {
        float v = g_sN[(b << 12) + i] * inv;
        g_sN[(b << 12) + i] = v;
        if (align_out) align_out[(size_t)(b << 12) + i] = v;
    }
}

// ---------------- context (fp32 value — bf16 here costs 1.6e-3 rel err) ---
__global__ void k_ctx(const float* __restrict__ value) {
    int tc = blockIdx.x, b = blockIdx.y, tid = threadIdx.x;
    const float4* vp =
        reinterpret_cast<const float4*>(value + ((size_t)b * Tz + tc * 128) * ENCz) + tid;
    const float* sp = g_sN + (b << 12) + (tc << 7);
    float4 acc = {0.f, 0.f, 0.f, 0.f};
#pragma unroll 4
    for (int t = 0; t < 128; t++) {
        float w = sp[t];
        float4 v = vp[(size_t)t * 256];
        acc.x += w * v.x;
        acc.y += w * v.y;
        acc.z += w * v.z;
        acc.w += w * v.w;
    }
    reinterpret_cast<float4*>(g_pctx + ((size_t)(b * 32 + tc) << 10))[tid] = acc;
}

__global__ void k_red(float* __restrict__ ctx_out) {
    int idx = blockIdx.x * 256 + threadIdx.x;
    int b = idx >> 10, e = idx & 1023;
    float s = 0.f;
#pragma unroll 8
    for (int tc = 0; tc < 32; tc++) s += g_pctx[((size_t)(b * 32 + tc) << 10) + e];
    ctx_out[idx] = s;
}

// ---------------- launch ----------------
extern "C" void kernel_launch(void* const* d_in, const int* in_sizes, int n_in,
                              void* d_out, int out_size) {
    const float* query  = (const float*)d_in[0];
    const float* value  = (const float*)d_in[1];
    const float* la     = (const float*)d_in[2];
    const float* conv_w = (const float*)d_in[3];
    const float* conv_b = (const float*)d_in[4];
    const float* WQ     = (const float*)d_in[5];
    const float* WV     = (const float*)d_in[6];
    const float* WU     = (const float*)d_in[7];
    const float* bias   = (const float*)d_in[8];
    const float* fcw    = (const float*)d_in[9];
    (void)in_sizes; (void)n_in;

    float* out = (float*)d_out;
    float* ctx_out = nullptr;
    float* align_out = nullptr;
    const int CTX_N = Bz * ENCz;
    const int ALN_N = Bz * Tz;
    if (out_size >= CTX_N + ALN_N) {
        ctx_out = out;
        align_out = out + CTX_N;
    } else if (out_size == ALN_N) {
        align_out = out;
    } else {
        ctx_out = out;
    }

    cudaFuncSetAttribute(k_gemm, cudaFuncAttributeMaxDynamicSharedMemorySize, SMEM_TOTAL);

    // k_gemm at graph index 3 (ncu capture lands there)
    k_qpb_cu<<<2049, 256>>>(query, WQ, bias, WU, conv_w, conv_b);
    k_prep_val<<<16384, 256>>>((const float4*)value);
    k_prep_wv<<<512, 256>>>((const float4*)WV);
    k_gemm<<<dim3(4, 1024), 256, SMEM_TOTAL>>>(la, fcw);
    k_score<<<32, 256>>>(align_out);
    if (ctx_out) {
        k_ctx<<<dim3(32, 32), 256>>>(value);
        k_red<<<128, 256>>>(ctx_out);
    }
}

// round 14
// speedup vs baseline: 1.0739x; 1.0739x over previous
#include <cuda_runtime.h>
#include <cuda_bf16.h>
#include <cstdint>

#define Bz 32
#define Tz 4096
#define DECz 1024
#define ENCz 1024
#define ATTNz 512
#define Kz 10

// ---------------- device scratch (no allocation allowed) ----------------
__device__ __nv_bfloat16 g_valh[(size_t)Bz * Tz * ENCz];  // 256 MB bf16 value
__device__ __nv_bfloat16 g_WVh[ATTNz * ENCz];             // bf16 WV, K-major
__device__ float g_qpb[Bz * ATTNz];                       // q·WQ^T + bias + cb
__device__ float g_cu0[ATTNz], g_cu1[ATTNz], g_cu2[ATTNz];
__device__ float g_ps[1024 * 4 * 128];                    // [mtile][nchunk][row]
__device__ float g_sN[Bz * Tz];
__device__ float g_pctx[Bz * 32 * ENCz];

// ---------------- PTX helpers ----------------
__device__ __forceinline__ uint32_t smem_u32(const void* p) {
    uint32_t a;
    asm("{ .reg .u64 t; cvta.to.shared.u64 t, %1; cvt.u32.u64 %0, t; }" : "=r"(a) : "l"(p));
    return a;
}
__device__ __forceinline__ void cpasync16(uint32_t sdst, const void* gsrc) {
    asm volatile("cp.async.cg.shared.global [%0], [%1], 16;\n" ::"r"(sdst), "l"(gsrc));
}
#define CP_COMMIT() asm volatile("cp.async.commit_group;\n")
template <int N>
__device__ __forceinline__ void cp_wait() {
    asm volatile("cp.async.wait_group %0;\n" ::"n"(N) : "memory");
}
__device__ __forceinline__ void ldsm4(uint32_t& r0, uint32_t& r1, uint32_t& r2,
                                      uint32_t& r3, uint32_t addr) {
    asm volatile("ldmatrix.sync.aligned.m8n8.x4.shared.b16 {%0,%1,%2,%3}, [%4];"
                 : "=r"(r0), "=r"(r1), "=r"(r2), "=r"(r3)
                 : "r"(addr));
}
__device__ __forceinline__ void mma16816(float c[4], const uint32_t a[4],
                                         uint32_t b0, uint32_t b1) {
    asm volatile(
        "mma.sync.aligned.m16n8k16.row.col.f32.bf16.bf16.f32 "
        "{%0,%1,%2,%3}, {%4,%5,%6,%7}, {%8,%9}, {%0,%1,%2,%3};\n"
        : "+f"(c[0]), "+f"(c[1]), "+f"(c[2]), "+f"(c[3])
        : "r"(a[0]), "r"(a[1]), "r"(a[2]), "r"(a[3]), "r"(b0), "r"(b1));
}
__device__ __forceinline__ float tanh_fast(float x) {
    float y;
    asm("tanh.approx.f32 %0, %1;" : "=f"(y) : "f"(x));
    return y;
}
__device__ __forceinline__ uint32_t swz(uint32_t off) {
    return off ^ ((off >> 3) & 0x70);
}

// ---------------- prep kernels (R10 exact — coalesced 1-line/8-thread) ----
__global__ void k_prep_val(const float4* __restrict__ V4) {
    size_t i = (size_t)blockIdx.x * blockDim.x + threadIdx.x;  // 16777216
    float4 v0 = V4[2 * i], v1 = V4[2 * i + 1];
    __nv_bfloat162 h0 = __floats2bfloat162_rn(v0.x, v0.y);
    __nv_bfloat162 h1 = __floats2bfloat162_rn(v0.z, v0.w);
    __nv_bfloat162 h2 = __floats2bfloat162_rn(v1.x, v1.y);
    __nv_bfloat162 h3 = __floats2bfloat162_rn(v1.z, v1.w);
    uint4 u;
    u.x = reinterpret_cast<uint32_t&>(h0);
    u.y = reinterpret_cast<uint32_t&>(h1);
    u.z = reinterpret_cast<uint32_t&>(h2);
    u.w = reinterpret_cast<uint32_t&>(h3);
    reinterpret_cast<uint4*>(g_valh)[i] = u;
}

__global__ void k_prep_wv(const float4* __restrict__ WV4) {
    int i = blockIdx.x * blockDim.x + threadIdx.x;
    float4 v = WV4[i];
    __nv_bfloat162 p0 = __floats2bfloat162_rn(v.x, v.y);
    __nv_bfloat162 p1 = __floats2bfloat162_rn(v.z, v.w);
    __nv_bfloat162* dst = reinterpret_cast<__nv_bfloat162*>(g_WVh);
    dst[2 * i + 0] = p0;
    dst[2 * i + 1] = p1;
}

// qpb (blocks 0..2047; includes bias + conv-bias fold) + cu tables (block 2048)
__global__ void k_qpb_cu(const float* __restrict__ q, const float* __restrict__ WQ,
                         const float* __restrict__ bias, const float* __restrict__ WU,
                         const float* __restrict__ cw, const float* __restrict__ cbv) {
    if (blockIdx.x == 2048) {
        for (int a = threadIdx.x; a < ATTNz; a += 256) {
            float s0 = 0.f, s1 = 0.f, s2 = 0.f;
#pragma unroll
            for (int k = 0; k < Kz; k++) {
                float w = WU[a * Kz + k];
                s0 += w * cw[k * 3 + 0];
                s1 += w * cw[k * 3 + 1];
                s2 += w * cw[k * 3 + 2];
            }
            g_cu0[a] = s0; g_cu1[a] = s1; g_cu2[a] = s2;
        }
        return;
    }
    int w = (blockIdx.x * blockDim.x + threadIdx.x) >> 5;
    int lane = threadIdx.x & 31;
    int b = w >> 9, a = w & 511;
    const float* qr = q + (size_t)b * DECz;
    const float* wr = WQ + (size_t)a * DECz;
    float s = 0.f;
    for (int d = lane; d < DECz; d += 32) s += qr[d] * wr[d];
#pragma unroll
    for (int o = 16; o; o >>= 1) s += __shfl_xor_sync(0xffffffffu, s, o);
    if (lane == 0) {
        float cb = 0.f;
#pragma unroll
        for (int k = 0; k < Kz; k++) cb += WU[a * Kz + k] * cbv[k];
        g_qpb[b * ATTNz + a] = s + bias[a] + cb;
    }
}

// ---------------- GEMM: 128x128 CTA tile, K=1024 in 16 chunks of 64 -------
// 3-stage cp.async pipeline, ldmatrix operands double-buffered across the 4
// k-steps of each chunk, 8 warps 4(M)x2(N), warp 32x64.  (R10 config — best;
// epilogue is register-allocation-fragile: do NOT restructure it.)
#define STAGE_A 16384
#define STAGE_B 16384
#define STAGE_BYTES 32768
#define OFF_SCORE (3 * STAGE_BYTES)
#define SMEM_TOTAL (3 * STAGE_BYTES + 1024)

__global__ __launch_bounds__(256, 2) void k_gemm(const float* __restrict__ la,
                                                 const float* __restrict__ fcw) {
    extern __shared__ char smem[];
    const uint32_t sbase = smem_u32(smem);
    const int tid = threadIdx.x, warp = tid >> 5, lane = tid & 31;
    const int nchunk = blockIdx.x;   // 0..3
    const int mtile = blockIdx.y;    // 0..1023
    const int wm = warp & 3, wn = warp >> 2;
    const int b = mtile >> 5;
    const int tt0 = (mtile & 31) << 7;
    const int g = lane >> 2, t4 = lane & 3;

    const char* Ag = reinterpret_cast<const char*>(g_valh) + (size_t)mtile * 128 * 2048;
    const char* Bg = reinterpret_cast<const char*>(g_WVh) + (size_t)nchunk * 128 * 2048;

    const int lr = tid >> 3, lseg = tid & 7;

    auto load_stage = [&](int c) {
        uint32_t dA = sbase + (c % 3) * STAGE_BYTES;
        uint32_t dB = dA + STAGE_A;
        const char* As = Ag + (size_t)lr * 2048 + c * 128 + lseg * 16;
        const char* Bs = Bg + (size_t)lr * 2048 + c * 128 + lseg * 16;
#pragma unroll
        for (int p = 0; p < 4; p++) {
            uint32_t off = swz((lr + 32 * p) * 128 + lseg * 16);
            cpasync16(dA + off, As + (size_t)(32 * p) * 2048);
            cpasync16(dB + off, Bs + (size_t)(32 * p) * 2048);
        }
        CP_COMMIT();
    };

    // ldmatrix per-lane base offsets (stage-relative); k-step advance is XOR
    // (swz(x + ks*32) == swz(x) ^ (ks*32) since pre-swizzle bits [5:6] are 0).
    const int lrow = lane & 15, lk = lane >> 4;
    uint32_t aoff[2], boff[4];
#pragma unroll
    for (int mt = 0; mt < 2; mt++)
        aoff[mt] = swz((wm * 32 + mt * 16 + lrow) * 128 + lk * 16);
#pragma unroll
    for (int nb = 0; nb < 4; nb++)
        boff[nb] = swz((wn * 64 + nb * 16 + lrow) * 128 + lk * 16);

    float acc[2][8][4];
#pragma unroll
    for (int mt = 0; mt < 2; mt++)
#pragma unroll
        for (int nt = 0; nt < 8; nt++)
#pragma unroll
            for (int j = 0; j < 4; j++) acc[mt][nt][j] = 0.f;

    load_stage(0);
    load_stage(1);

    for (int c = 0; c < 16; c++) {
        if (c < 15) cp_wait<1>(); else cp_wait<0>();
        __syncthreads();
        if (c + 2 < 16) load_stage(c + 2);

        uint32_t stA = sbase + (c % 3) * STAGE_BYTES;
        uint32_t stB = stA + STAGE_A;

        // fragment double buffers across k-steps
        uint32_t af[2][2][4];
        uint32_t qf[2][4][4];
        ldsm4(af[0][0][0], af[0][0][1], af[0][0][2], af[0][0][3], stA + aoff[0]);
        ldsm4(af[0][1][0], af[0][1][1], af[0][1][2], af[0][1][3], stA + aoff[1]);
#pragma unroll
        for (int nb = 0; nb < 4; nb++)
            ldsm4(qf[0][nb][0], qf[0][nb][1], qf[0][nb][2], qf[0][nb][3],
                  stB + boff[nb]);
#pragma unroll
        for (int ks = 0; ks < 4; ks++) {
            const int cur = ks & 1, nxt = cur ^ 1;
            if (ks < 3) {
                const uint32_t kx = (ks + 1) * 32;
                ldsm4(af[nxt][0][0], af[nxt][0][1], af[nxt][0][2], af[nxt][0][3],
                      stA + (aoff[0] ^ kx));
                ldsm4(af[nxt][1][0], af[nxt][1][1], af[nxt][1][2], af[nxt][1][3],
                      stA + (aoff[1] ^ kx));
#pragma unroll
                for (int nb = 0; nb < 4; nb++)
                    ldsm4(qf[nxt][nb][0], qf[nxt][nb][1], qf[nxt][nb][2],
                          qf[nxt][nb][3], stB + (boff[nb] ^ kx));
            }
#pragma unroll
            for (int nb = 0; nb < 4; nb++) {
#pragma unroll
                for (int mt = 0; mt < 2; mt++) {
                    mma16816(acc[mt][2 * nb + 0], af[cur][mt], qf[cur][nb][0],
                             qf[cur][nb][2]);
                    mma16816(acc[mt][2 * nb + 1], af[cur][mt], qf[cur][nb][1],
                             qf[cur][nb][3]);
                }
            }
        }
    }

    // -------- epilogue: tanh + fc_w dot, partial over this nchunk --------
    // (exact R10 form — register-allocation-fragile, do not restructure)
    const float* lab = la + (size_t)b * Tz;
    float lm[4], l0[4], lp[4];
#pragma unroll
    for (int i = 0; i < 4; i++) {
        int r = 32 * wm + 16 * (i >> 1) + g + 8 * (i & 1);
        int t = tt0 + r;
        l0[i] = lab[t];
        lm[i] = (t > 0) ? lab[t - 1] : 0.f;
        lp[i] = (t < Tz - 1) ? lab[t + 1] : 0.f;
    }
    float rsum[4] = {0.f, 0.f, 0.f, 0.f};
#pragma unroll
    for (int mt = 0; mt < 2; mt++) {
#pragma unroll
        for (int nt = 0; nt < 8; nt++) {
#pragma unroll
            for (int j = 0; j < 4; j++) {
                int ridx = (mt << 1) | (j >> 1);
                int col = 64 * wn + 8 * nt + 2 * t4 + (j & 1);
                int a = (nchunk << 7) + col;
                float x = acc[mt][nt][j] + g_qpb[(b << 9) + a] +
                          g_cu0[a] * lm[ridx] + g_cu1[a] * l0[ridx] +
                          g_cu2[a] * lp[ridx];
                rsum[ridx] += fcw[a] * tanh_fast(x);
            }
        }
    }
    __syncthreads();
    float* scoreSm = reinterpret_cast<float*>(smem + OFF_SCORE);
#pragma unroll
    for (int i = 0; i < 4; i++) {
        float v = rsum[i];
        v += __shfl_xor_sync(0xffffffffu, v, 1);
        v += __shfl_xor_sync(0xffffffffu, v, 2);
        if (t4 == 0) {
            int r = 32 * wm + 16 * (i >> 1) + g + 8 * (i & 1);
            scoreSm[r * 2 + wn] = v;
        }
    }
    __syncthreads();
    if (tid < 128) {
        g_ps[((size_t)(mtile * 4 + nchunk)) * 128 + tid] =
            scoreSm[tid * 2 + 0] + scoreSm[tid * 2 + 1];
    }
}

// ---------------- sigmoid + normalize (deterministic) ----------------
__global__ void k_score(float* align_out) {
    int b = blockIdx.x, tid = threadIdx.x;
    __shared__ float red[256];
    float lsum = 0.f;
    for (int i = tid; i < Tz; i += 256) {
        int mtile = (b << 5) + (i >> 7);
        int r = i & 127;
        const float* p = g_ps + (size_t)mtile * 4 * 128 + r;
        float sraw = p[0] + p[128] + p[256] + p[384];
        float s = 1.f / (1.f + expf(-sraw));
        g_sN[(b << 12) + i] = s;
        lsum += s;
    }
    red[tid] = lsum;
    __syncthreads();
#pragma unroll
    for (int o = 128; o; o >>= 1) {
        if (tid < o) red[tid] += red[tid + o];
        __syncthreads();
    }
    float inv = 1.f / red[0];
    for (int i = tid; i < Tz; i += 256) {
        float v = g_sN[(b << 12) + i] * inv;
        g_sN[(b << 12) + i] = v;
        if (align_out) align_out[(size_t)(b << 12) + i] = v;
    }
}

// ---------------- context (fp32 value — bf16 here costs 1.6e-3 rel err) ---
__global__ void k_ctx(const float* __restrict__ value) {
    int tc = blockIdx.x, b = blockIdx.y, tid = threadIdx.x;
    const float4* vp =
        reinterpret_cast<const float4*>(value + ((size_t)b * Tz + tc * 128) * ENCz) + tid;
    const float* sp = g_sN + (b << 12) + (tc << 7);
    float4 acc = {0.f, 0.f, 0.f, 0.f};
#pragma unroll 4
    for (int t = 0; t < 128; t++) {
        float w = sp[t];
        float4 v = vp[(size_t)t * 256];
        acc.x += w * v.x;
        acc.y += w * v.y;
        acc.z += w * v.z;
        acc.w += w * v.w;
    }
    reinterpret_cast<float4*>(g_pctx + ((size_t)(b * 32 + tc) << 10))[tid] = acc;
}

__global__ void k_red(float* __restrict__ ctx_out) {
    int idx = blockIdx.x * 256 + threadIdx.x;
    int b = idx >> 10, e = idx & 1023;
    float s = 0.f;
#pragma unroll 8
    for (int tc = 0; tc < 32; tc++) s += g_pctx[((size_t)(b * 32 + tc) << 10) + e];
    ctx_out[idx] = s;
}

// ---------------- launch ----------------
extern "C" void kernel_launch(void* const* d_in, const int* in_sizes, int n_in,
                              void* d_out, int out_size) {
    const float* query  = (const float*)d_in[0];
    const float* value  = (const float*)d_in[1];
    const float* la     = (const float*)d_in[2];
    const float* conv_w = (const float*)d_in[3];
    const float* conv_b = (const float*)d_in[4];
    const float* WQ     = (const float*)d_in[5];
    const float* WV     = (const float*)d_in[6];
    const float* WU     = (const float*)d_in[7];
    const float* bias   = (const float*)d_in[8];
    const float* fcw    = (const float*)d_in[9];
    (void)in_sizes; (void)n_in;

    float* out = (float*)d_out;
    float* ctx_out = nullptr;
    float* align_out = nullptr;
    const int CTX_N = Bz * ENCz;
    const int ALN_N = Bz * Tz;
    if (out_size >= CTX_N + ALN_N) {
        ctx_out = out;
        align_out = out + CTX_N;
    } else if (out_size == ALN_N) {
        align_out = out;
    } else {
        ctx_out = out;
    }

    cudaFuncSetAttribute(k_gemm, cudaFuncAttributeMaxDynamicSharedMemorySize, SMEM_TOTAL);

    // k_gemm at graph index 3 (ncu capture lands there)
    k_qpb_cu<<<2049, 256>>>(query, WQ, bias, WU, conv_w, conv_b);
    k_prep_val<<<65536, 256>>>((const float4*)value);
    k_prep_wv<<<512, 256>>>((const float4*)WV);
    k_gemm<<<dim3(4, 1024), 256, SMEM_TOTAL>>>(la, fcw);
    k_score<<<32, 256>>>(align_out);
    if (ctx_out) {
        k_ctx<<<dim3(32, 32), 256>>>(value);
        k_red<<<128, 256>>>(ctx_out);
    }
}

// round 15
// speedup vs baseline: 1.0807x; 1.0064x over previous
#include <cuda_runtime.h>
#include <cuda_bf16.h>
#include <cstdint>

#define Bz 32
#define Tz 4096
#define DECz 1024
#define ENCz 1024
#define ATTNz 512
#define Kz 10

// ---------------- device scratch (no allocation allowed) ----------------
__device__ __nv_bfloat16 g_valh[(size_t)Bz * Tz * ENCz];  // 256 MB bf16 value
__device__ __nv_bfloat16 g_WVh[ATTNz * ENCz];             // bf16 WV, K-major
__device__ float g_qpb[Bz * ATTNz];                       // q·WQ^T + bias + cb
__device__ float g_cu0[ATTNz], g_cu1[ATTNz], g_cu2[ATTNz];
__device__ float g_ps[1024 * 4 * 128];                    // [mtile][nchunk][row]
__device__ float g_sN[Bz * Tz];
__device__ float g_pctx[Bz * 32 * ENCz];

// ---------------- PTX helpers ----------------
__device__ __forceinline__ uint32_t smem_u32(const void* p) {
    uint32_t a;
    asm("{ .reg .u64 t; cvta.to.shared.u64 t, %1; cvt.u32.u64 %0, t; }" : "=r"(a) : "l"(p));
    return a;
}
__device__ __forceinline__ void cpasync16(uint32_t sdst, const void* gsrc) {
    asm volatile("cp.async.cg.shared.global [%0], [%1], 16;\n" ::"r"(sdst), "l"(gsrc));
}
#define CP_COMMIT() asm volatile("cp.async.commit_group;\n")
template <int N>
__device__ __forceinline__ void cp_wait() {
    asm volatile("cp.async.wait_group %0;\n" ::"n"(N) : "memory");
}
__device__ __forceinline__ void ldsm4(uint32_t& r0, uint32_t& r1, uint32_t& r2,
                                      uint32_t& r3, uint32_t addr) {
    asm volatile("ldmatrix.sync.aligned.m8n8.x4.shared.b16 {%0,%1,%2,%3}, [%4];"
                 : "=r"(r0), "=r"(r1), "=r"(r2), "=r"(r3)
                 : "r"(addr));
}
__device__ __forceinline__ void mma16816(float c[4], const uint32_t a[4],
                                         uint32_t b0, uint32_t b1) {
    asm volatile(
        "mma.sync.aligned.m16n8k16.row.col.f32.bf16.bf16.f32 "
        "{%0,%1,%2,%3}, {%4,%5,%6,%7}, {%8,%9}, {%0,%1,%2,%3};\n"
        : "+f"(c[0]), "+f"(c[1]), "+f"(c[2]), "+f"(c[3])
        : "r"(a[0]), "r"(a[1]), "r"(a[2]), "r"(a[3]), "r"(b0), "r"(b1));
}
__device__ __forceinline__ float tanh_fast(float x) {
    float y;
    asm("tanh.approx.f32 %0, %1;" : "=f"(y) : "f"(x));
    return y;
}
__device__ __forceinline__ uint32_t swz(uint32_t off) {
    return off ^ ((off >> 3) & 0x70);
}

// ---------------- prep kernels (coalesced 1-line/8-thread) ----------------
// chunked: base is a uint4 index offset (chunk = 256 mtiles = 4194304 uint4)
__global__ void k_prep_val(const float4* __restrict__ V4, size_t base) {
    size_t i = base + (size_t)blockIdx.x * blockDim.x + threadIdx.x;
    float4 v0 = V4[2 * i], v1 = V4[2 * i + 1];
    __nv_bfloat162 h0 = __floats2bfloat162_rn(v0.x, v0.y);
    __nv_bfloat162 h1 = __floats2bfloat162_rn(v0.z, v0.w);
    __nv_bfloat162 h2 = __floats2bfloat162_rn(v1.x, v1.y);
    __nv_bfloat162 h3 = __floats2bfloat162_rn(v1.z, v1.w);
    uint4 u;
    u.x = reinterpret_cast<uint32_t&>(h0);
    u.y = reinterpret_cast<uint32_t&>(h1);
    u.z = reinterpret_cast<uint32_t&>(h2);
    u.w = reinterpret_cast<uint32_t&>(h3);
    reinterpret_cast<uint4*>(g_valh)[i] = u;
}

__global__ void k_prep_wv(const float4* __restrict__ WV4) {
    int i = blockIdx.x * blockDim.x + threadIdx.x;
    float4 v = WV4[i];
    __nv_bfloat162 p0 = __floats2bfloat162_rn(v.x, v.y);
    __nv_bfloat162 p1 = __floats2bfloat162_rn(v.z, v.w);
    __nv_bfloat162* dst = reinterpret_cast<__nv_bfloat162*>(g_WVh);
    dst[2 * i + 0] = p0;
    dst[2 * i + 1] = p1;
}

// qpb (blocks 0..2047; includes bias + conv-bias fold) + cu tables (block 2048)
__global__ void k_qpb_cu(const float* __restrict__ q, const float* __restrict__ WQ,
                         const float* __restrict__ bias, const float* __restrict__ WU,
                         const float* __restrict__ cw, const float* __restrict__ cbv) {
    if (blockIdx.x == 2048) {
        for (int a = threadIdx.x; a < ATTNz; a += 256) {
            float s0 = 0.f, s1 = 0.f, s2 = 0.f;
#pragma unroll
            for (int k = 0; k < Kz; k++) {
                float w = WU[a * Kz + k];
                s0 += w * cw[k * 3 + 0];
                s1 += w * cw[k * 3 + 1];
                s2 += w * cw[k * 3 + 2];
            }
            g_cu0[a] = s0; g_cu1[a] = s1; g_cu2[a] = s2;
        }
        return;
    }
    int w = (blockIdx.x * blockDim.x + threadIdx.x) >> 5;
    int lane = threadIdx.x & 31;
    int b = w >> 9, a = w & 511;
    const float* qr = q + (size_t)b * DECz;
    const float* wr = WQ + (size_t)a * DECz;
    float s = 0.f;
    for (int d = lane; d < DECz; d += 32) s += qr[d] * wr[d];
#pragma unroll
    for (int o = 16; o; o >>= 1) s += __shfl_xor_sync(0xffffffffu, s, o);
    if (lane == 0) {
        float cb = 0.f;
#pragma unroll
        for (int k = 0; k < Kz; k++) cb += WU[a * Kz + k] * cbv[k];
        g_qpb[b * ATTNz + a] = s + bias[a] + cb;
    }
}

// ---------------- GEMM: 128x128 CTA tile, K=1024 in 16 chunks of 64 -------
// 3-stage cp.async pipeline, ldmatrix operands double-buffered across the 4
// k-steps of each chunk, 8 warps 4(M)x2(N), warp 32x64.  (R10 config — best;
// epilogue is register-allocation-fragile: do NOT restructure it.)
// mtile0 offsets blockIdx.y for chunked launches.
#define STAGE_A 16384
#define STAGE_B 16384
#define STAGE_BYTES 32768
#define OFF_SCORE (3 * STAGE_BYTES)
#define SMEM_TOTAL (3 * STAGE_BYTES + 1024)

__global__ __launch_bounds__(256, 2) void k_gemm(const float* __restrict__ la,
                                                 const float* __restrict__ fcw,
                                                 int mtile0) {
    extern __shared__ char smem[];
    const uint32_t sbase = smem_u32(smem);
    const int tid = threadIdx.x, warp = tid >> 5, lane = tid & 31;
    const int nchunk = blockIdx.x;            // 0..3
    const int mtile = blockIdx.y + mtile0;    // 0..1023
    const int wm = warp & 3, wn = warp >> 2;
    const int b = mtile >> 5;
    const int tt0 = (mtile & 31) << 7;
    const int g = lane >> 2, t4 = lane & 3;

    const char* Ag = reinterpret_cast<const char*>(g_valh) + (size_t)mtile * 128 * 2048;
    const char* Bg = reinterpret_cast<const char*>(g_WVh) + (size_t)nchunk * 128 * 2048;

    const int lr = tid >> 3, lseg = tid & 7;

    auto load_stage = [&](int c) {
        uint32_t dA = sbase + (c % 3) * STAGE_BYTES;
        uint32_t dB = dA + STAGE_A;
        const char* As = Ag + (size_t)lr * 2048 + c * 128 + lseg * 16;
        const char* Bs = Bg + (size_t)lr * 2048 + c * 128 + lseg * 16;
#pragma unroll
        for (int p = 0; p < 4; p++) {
            uint32_t off = swz((lr + 32 * p) * 128 + lseg * 16);
            cpasync16(dA + off, As + (size_t)(32 * p) * 2048);
            cpasync16(dB + off, Bs + (size_t)(32 * p) * 2048);
        }
        CP_COMMIT();
    };

    // ldmatrix per-lane base offsets (stage-relative); k-step advance is XOR
    // (swz(x + ks*32) == swz(x) ^ (ks*32) since pre-swizzle bits [5:6] are 0).
    const int lrow = lane & 15, lk = lane >> 4;
    uint32_t aoff[2], boff[4];
#pragma unroll
    for (int mt = 0; mt < 2; mt++)
        aoff[mt] = swz((wm * 32 + mt * 16 + lrow) * 128 + lk * 16);
#pragma unroll
    for (int nb = 0; nb < 4; nb++)
        boff[nb] = swz((wn * 64 + nb * 16 + lrow) * 128 + lk * 16);

    float acc[2][8][4];
#pragma unroll
    for (int mt = 0; mt < 2; mt++)
#pragma unroll
        for (int nt = 0; nt < 8; nt++)
#pragma unroll
            for (int j = 0; j < 4; j++) acc[mt][nt][j] = 0.f;

    load_stage(0);
    load_stage(1);

    for (int c = 0; c < 16; c++) {
        if (c < 15) cp_wait<1>(); else cp_wait<0>();
        __syncthreads();
        if (c + 2 < 16) load_stage(c + 2);

        uint32_t stA = sbase + (c % 3) * STAGE_BYTES;
        uint32_t stB = stA + STAGE_A;

        // fragment double buffers across k-steps
        uint32_t af[2][2][4];
        uint32_t qf[2][4][4];
        ldsm4(af[0][0][0], af[0][0][1], af[0][0][2], af[0][0][3], stA + aoff[0]);
        ldsm4(af[0][1][0], af[0][1][1], af[0][1][2], af[0][1][3], stA + aoff[1]);
#pragma unroll
        for (int nb = 0; nb < 4; nb++)
            ldsm4(qf[0][nb][0], qf[0][nb][1], qf[0][nb][2], qf[0][nb][3],
                  stB + boff[nb]);
#pragma unroll
        for (int ks = 0; ks < 4; ks++) {
            const int cur = ks & 1, nxt = cur ^ 1;
            if (ks < 3) {
                const uint32_t kx = (ks + 1) * 32;
                ldsm4(af[nxt][0][0], af[nxt][0][1], af[nxt][0][2], af[nxt][0][3],
                      stA + (aoff[0] ^ kx));
                ldsm4(af[nxt][1][0], af[nxt][1][1], af[nxt][1][2], af[nxt][1][3],
                      stA + (aoff[1] ^ kx));
#pragma unroll
                for (int nb = 0; nb < 4; nb++)
                    ldsm4(qf[nxt][nb][0], qf[nxt][nb][1], qf[nxt][nb][2],
                          qf[nxt][nb][3], stB + (boff[nb] ^ kx));
            }
#pragma unroll
            for (int nb = 0; nb < 4; nb++) {
#pragma unroll
                for (int mt = 0; mt < 2; mt++) {
                    mma16816(acc[mt][2 * nb + 0], af[cur][mt], qf[cur][nb][0],
                             qf[cur][nb][2]);
                    mma16816(acc[mt][2 * nb + 1], af[cur][mt], qf[cur][nb][1],
                             qf[cur][nb][3]);
                }
            }
        }
    }

    // -------- epilogue: tanh + fc_w dot, partial over this nchunk --------
    // (exact R10 form — register-allocation-fragile, do not restructure)
    const float* lab = la + (size_t)b * Tz;
    float lm[4], l0[4], lp[4];
#pragma unroll
    for (int i = 0; i < 4; i++) {
        int r = 32 * wm + 16 * (i >> 1) + g + 8 * (i & 1);
        int t = tt0 + r;
        l0[i] = lab[t];
        lm[i] = (t > 0) ? lab[t - 1] : 0.f;
        lp[i] = (t < Tz - 1) ? lab[t + 1] : 0.f;
    }
    float rsum[4] = {0.f, 0.f, 0.f, 0.f};
#pragma unroll
    for (int mt = 0; mt < 2; mt++) {
#pragma unroll
        for (int nt = 0; nt < 8; nt++) {
#pragma unroll
            for (int j = 0; j < 4; j++) {
                int ridx = (mt << 1) | (j >> 1);
                int col = 64 * wn + 8 * nt + 2 * t4 + (j & 1);
                int a = (nchunk << 7) + col;
                float x = acc[mt][nt][j] + g_qpb[(b << 9) + a] +
                          g_cu0[a] * lm[ridx] + g_cu1[a] * l0[ridx] +
                          g_cu2[a] * lp[ridx];
                rsum[ridx] += fcw[a] * tanh_fast(x);
            }
        }
    }
    __syncthreads();
    float* scoreSm = reinterpret_cast<float*>(smem + OFF_SCORE);
#pragma unroll
    for (int i = 0; i < 4; i++) {
        float v = rsum[i];
        v += __shfl_xor_sync(0xffffffffu, v, 1);
        v += __shfl_xor_sync(0xffffffffu, v, 2);
        if (t4 == 0) {
            int r = 32 * wm + 16 * (i >> 1) + g + 8 * (i & 1);
            scoreSm[r * 2 + wn] = v;
        }
    }
    __syncthreads();
    if (tid < 128) {
        g_ps[((size_t)(mtile * 4 + nchunk)) * 128 + tid] =
            scoreSm[tid * 2 + 0] + scoreSm[tid * 2 + 1];
    }
}

// ---------------- sigmoid + normalize (deterministic) ----------------
__global__ void k_score(float* align_out) {
    int b = blockIdx.x, tid = threadIdx.x;
    __shared__ float red[256];
    float lsum = 0.f;
    for (int i = tid; i < Tz; i += 256) {
        int mtile = (b << 5) + (i >> 7);
        int r = i & 127;
        const float* p = g_ps + (size_t)mtile * 4 * 128 + r;
        float sraw = p[0] + p[128] + p[256] + p[384];
        float s = 1.f / (1.f + expf(-sraw));
        g_sN[(b << 12) + i] = s;
        lsum += s;
    }
    red[tid] = lsum;
    __syncthreads();
#pragma unroll
    for (int o = 128; o; o >>= 1) {
        if (tid < o) red[tid] += red[tid + o];
        __syncthreads();
    }
    float inv = 1.f / red[0];
    for (int i = tid; i < Tz; i += 256) {
        float v = g_sN[(b << 12) + i] * inv;
        g_sN[(b << 12) + i] = v;
        if (align_out) align_out[(size_t)(b << 12) + i] = v;
    }
}

// ---------------- context (fp32 value — bf16 here costs 1.6e-3 rel err) ---
__global__ void k_ctx(const float* __restrict__ value) {
    int tc = blockIdx.x, b = blockIdx.y, tid = threadIdx.x;
    const float4* vp =
        reinterpret_cast<const float4*>(value + ((size_t)b * Tz + tc * 128) * ENCz) + tid;
    const float* sp = g_sN + (b << 12) + (tc << 7);
    float4 acc = {0.f, 0.f, 0.f, 0.f};
#pragma unroll 4
    for (int t = 0; t < 128; t++) {
        float w = sp[t];
        float4 v = vp[(size_t)t * 256];
        acc.x += w * v.x;
        acc.y += w * v.y;
        acc.z += w * v.z;
        acc.w += w * v.w;
    }
    reinterpret_cast<float4*>(g_pctx + ((size_t)(b * 32 + tc) << 10))[tid] = acc;
}

__global__ void k_red(float* __restrict__ ctx_out) {
    int idx = blockIdx.x * 256 + threadIdx.x;
    int b = idx >> 10, e = idx & 1023;
    float s = 0.f;
#pragma unroll 8
    for (int tc = 0; tc < 32; tc++) s += g_pctx[((size_t)(b * 32 + tc) << 10) + e];
    ctx_out[idx] = s;
}

// ---------------- launch: fork-join overlap of prep_val and gemm ----------
extern "C" void kernel_launch(void* const* d_in, const int* in_sizes, int n_in,
                              void* d_out, int out_size) {
    const float* query  = (const float*)d_in[0];
    const float* value  = (const float*)d_in[1];
    const float* la     = (const float*)d_in[2];
    const float* conv_w = (const float*)d_in[3];
    const float* conv_b = (const float*)d_in[4];
    const float* WQ     = (const float*)d_in[5];
    const float* WV     = (const float*)d_in[6];
    const float* WU     = (const float*)d_in[7];
    const float* bias   = (const float*)d_in[8];
    const float* fcw    = (const float*)d_in[9];
    (void)in_sizes; (void)n_in;

    float* out = (float*)d_out;
    float* ctx_out = nullptr;
    float* align_out = nullptr;
    const int CTX_N = Bz * ENCz;
    const int ALN_N = Bz * Tz;
    if (out_size >= CTX_N + ALN_N) {
        ctx_out = out;
        align_out = out + CTX_N;
    } else if (out_size == ALN_N) {
        align_out = out;
    } else {
        ctx_out = out;
    }

    cudaFuncSetAttribute(k_gemm, cudaFuncAttributeMaxDynamicSharedMemorySize, SMEM_TOTAL);

    // fork stream + events (host resources; created per call, intentionally
    // not destroyed while capture may still reference them — bounded leak,
    // kernel_launch is called only a few times, never in the timed replay)
    cudaStream_t s2;
    cudaEvent_t ev[4], evDone;
    bool forked = (cudaStreamCreateWithFlags(&s2, cudaStreamNonBlocking) == cudaSuccess);
    if (forked) {
        for (int i = 0; i < 4; i++)
            forked = forked &&
                     (cudaEventCreateWithFlags(&ev[i], cudaEventDisableTiming) == cudaSuccess);
        forked = forked &&
                 (cudaEventCreateWithFlags(&evDone, cudaEventDisableTiming) == cudaSuccess);
    }

    // qpb + cu + WV prep first (gemm chunks need them; ordered via events)
    k_qpb_cu<<<2049, 256>>>(query, WQ, bias, WU, conv_w, conv_b);
    k_prep_wv<<<512, 256>>>((const float4*)WV);

    if (forked) {
        // 4 chunks of 256 mtiles: prep chunk i on stream 0, gemm chunk i on s2
        for (int i = 0; i < 4; i++) {
            k_prep_val<<<16384, 256>>>((const float4*)value, (size_t)i * 4194304);
            cudaEventRecord(ev[i], 0);
            cudaStreamWaitEvent(s2, ev[i], 0);
            k_gemm<<<dim3(4, 256), 256, SMEM_TOTAL, s2>>>(la, fcw, i * 256);
        }
        cudaEventRecord(evDone, s2);
        cudaStreamWaitEvent((cudaStream_t)0, evDone, 0);
    } else {
        // fallback: fully serial (R14 behavior)
        for (int i = 0; i < 4; i++)
            k_prep_val<<<16384, 256>>>((const float4*)value, (size_t)i * 4194304);
        k_gemm<<<dim3(4, 1024), 256, SMEM_TOTAL>>>(la, fcw, 0);
    }

    k_score<<<32, 256>>>(align_out);
    if (ctx_out) {
        k_ctx<<<dim3(32, 32), 256>>>(value);
        k_red<<<128, 256>>>(ctx_out);
    }
}

// round 17
// speedup vs baseline: 1.0819x; 1.0011x over previous
#include <cuda_runtime.h>
#include <cuda_bf16.h>
#include <cstdint>

#define Bz 32
#define Tz 4096
#define DECz 1024
#define ENCz 1024
#define ATTNz 512
#define Kz 10

// ---------------- device scratch (no allocation allowed) ----------------
__device__ __nv_bfloat16 g_valh[(size_t)Bz * Tz * ENCz];  // 256 MB bf16 value
__device__ __nv_bfloat16 g_WVh[ATTNz * ENCz];             // bf16 WV, K-major
__device__ float g_qpb[Bz * ATTNz];                       // q·WQ^T + bias + cb
__device__ float g_cu0[ATTNz], g_cu1[ATTNz], g_cu2[ATTNz];
__device__ float g_ps[1024 * 4 * 128];                    // [mtile][nchunk][row]
__device__ float g_sN[Bz * Tz];
__device__ float g_pctx[Bz * 32 * ENCz];

// ---------------- PTX helpers ----------------
__device__ __forceinline__ uint32_t smem_u32(const void* p) {
    uint32_t a;
    asm("{ .reg .u64 t; cvta.to.shared.u64 t, %1; cvt.u32.u64 %0, t; }" : "=r"(a) : "l"(p));
    return a;
}
__device__ __forceinline__ void cpasync16(uint32_t sdst, const void* gsrc) {
    asm volatile("cp.async.cg.shared.global [%0], [%1], 16;\n" ::"r"(sdst), "l"(gsrc));
}
#define CP_COMMIT() asm volatile("cp.async.commit_group;\n")
template <int N>
__device__ __forceinline__ void cp_wait() {
    asm volatile("cp.async.wait_group %0;\n" ::"n"(N) : "memory");
}
__device__ __forceinline__ void ldsm4(uint32_t& r0, uint32_t& r1, uint32_t& r2,
                                      uint32_t& r3, uint32_t addr) {
    asm volatile("ldmatrix.sync.aligned.m8n8.x4.shared.b16 {%0,%1,%2,%3}, [%4];"
                 : "=r"(r0), "=r"(r1), "=r"(r2), "=r"(r3)
                 : "r"(addr));
}
__device__ __forceinline__ void mma16816(float c[4], const uint32_t a[4],
                                         uint32_t b0, uint32_t b1) {
    asm volatile(
        "mma.sync.aligned.m16n8k16.row.col.f32.bf16.bf16.f32 "
        "{%0,%1,%2,%3}, {%4,%5,%6,%7}, {%8,%9}, {%0,%1,%2,%3};\n"
        : "+f"(c[0]), "+f"(c[1]), "+f"(c[2]), "+f"(c[3])
        : "r"(a[0]), "r"(a[1]), "r"(a[2]), "r"(a[3]), "r"(b0), "r"(b1));
}
__device__ __forceinline__ float tanh_fast(float x) {
    float y;
    asm("tanh.approx.f32 %0, %1;" : "=f"(y) : "f"(x));
    return y;
}
__device__ __forceinline__ uint32_t swz(uint32_t off) {
    return off ^ ((off >> 3) & 0x70);
}

// ---------------- prep kernels (coalesced 1-line/8-thread) ----------------
__global__ void k_prep_val(const float4* __restrict__ V4, size_t base) {
    size_t i = base + (size_t)blockIdx.x * blockDim.x + threadIdx.x;
    float4 v0 = V4[2 * i], v1 = V4[2 * i + 1];
    __nv_bfloat162 h0 = __floats2bfloat162_rn(v0.x, v0.y);
    __nv_bfloat162 h1 = __floats2bfloat162_rn(v0.z, v0.w);
    __nv_bfloat162 h2 = __floats2bfloat162_rn(v1.x, v1.y);
    __nv_bfloat162 h3 = __floats2bfloat162_rn(v1.z, v1.w);
    uint4 u;
    u.x = reinterpret_cast<uint32_t&>(h0);
    u.y = reinterpret_cast<uint32_t&>(h1);
    u.z = reinterpret_cast<uint32_t&>(h2);
    u.w = reinterpret_cast<uint32_t&>(h3);
    reinterpret_cast<uint4*>(g_valh)[i] = u;
}

__global__ void k_prep_wv(const float4* __restrict__ WV4) {
    int i = blockIdx.x * blockDim.x + threadIdx.x;
    float4 v = WV4[i];
    __nv_bfloat162 p0 = __floats2bfloat162_rn(v.x, v.y);
    __nv_bfloat162 p1 = __floats2bfloat162_rn(v.z, v.w);
    __nv_bfloat162* dst = reinterpret_cast<__nv_bfloat162*>(g_WVh);
    dst[2 * i + 0] = p0;
    dst[2 * i + 1] = p1;
}

// qpb (blocks 0..2047; includes bias + conv-bias fold) + cu tables (block 2048)
__global__ void k_qpb_cu(const float* __restrict__ q, const float* __restrict__ WQ,
                         const float* __restrict__ bias, const float* __restrict__ WU,
                         const float* __restrict__ cw, const float* __restrict__ cbv) {
    if (blockIdx.x == 2048) {
        for (int a = threadIdx.x; a < ATTNz; a += 256) {
            float s0 = 0.f, s1 = 0.f, s2 = 0.f;
#pragma unroll
            for (int k = 0; k < Kz; k++) {
                float w = WU[a * Kz + k];
                s0 += w * cw[k * 3 + 0];
                s1 += w * cw[k * 3 + 1];
                s2 += w * cw[k * 3 + 2];
            }
            g_cu0[a] = s0; g_cu1[a] = s1; g_cu2[a] = s2;
        }
        return;
    }
    int w = (blockIdx.x * blockDim.x + threadIdx.x) >> 5;
    int lane = threadIdx.x & 31;
    int b = w >> 9, a = w & 511;
    const float* qr = q + (size_t)b * DECz;
    const float* wr = WQ + (size_t)a * DECz;
    float s = 0.f;
    for (int d = lane; d < DECz; d += 32) s += qr[d] * wr[d];
#pragma unroll
    for (int o = 16; o; o >>= 1) s += __shfl_xor_sync(0xffffffffu, s, o);
    if (lane == 0) {
        float cb = 0.f;
#pragma unroll
        for (int k = 0; k < Kz; k++) cb += WU[a * Kz + k] * cbv[k];
        g_qpb[b * ATTNz + a] = s + bias[a] + cb;
    }
}

// ---------------- GEMM: 128x128 CTA tile, K=1024 in 16 chunks of 64 -------
// (R10 config — best; epilogue register-allocation-fragile: do NOT touch.)
#define STAGE_A 16384
#define STAGE_B 16384
#define STAGE_BYTES 32768
#define OFF_SCORE (3 * STAGE_BYTES)
#define SMEM_TOTAL (3 * STAGE_BYTES + 1024)

__global__ __launch_bounds__(256, 2) void k_gemm(const float* __restrict__ la,
                                                 const float* __restrict__ fcw,
                                                 int mtile0) {
    extern __shared__ char smem[];
    const uint32_t sbase = smem_u32(smem);
    const int tid = threadIdx.x, warp = tid >> 5, lane = tid & 31;
    const int nchunk = blockIdx.x;            // 0..3
    const int mtile = blockIdx.y + mtile0;    // 0..1023
    const int wm = warp & 3, wn = warp >> 2;
    const int b = mtile >> 5;
    const int tt0 = (mtile & 31) << 7;
    const int g = lane >> 2, t4 = lane & 3;

    const char* Ag = reinterpret_cast<const char*>(g_valh) + (size_t)mtile * 128 * 2048;
    const char* Bg = reinterpret_cast<const char*>(g_WVh) + (size_t)nchunk * 128 * 2048;

    const int lr = tid >> 3, lseg = tid & 7;

    auto load_stage = [&](int c) {
        uint32_t dA = sbase + (c % 3) * STAGE_BYTES;
        uint32_t dB = dA + STAGE_A;
        const char* As = Ag + (size_t)lr * 2048 + c * 128 + lseg * 16;
        const char* Bs = Bg + (size_t)lr * 2048 + c * 128 + lseg * 16;
#pragma unroll
        for (int p = 0; p < 4; p++) {
            uint32_t off = swz((lr + 32 * p) * 128 + lseg * 16);
            cpasync16(dA + off, As + (size_t)(32 * p) * 2048);
            cpasync16(dB + off, Bs + (size_t)(32 * p) * 2048);
        }
        CP_COMMIT();
    };

    const int lrow = lane & 15, lk = lane >> 4;
    uint32_t aoff[2], boff[4];
#pragma unroll
    for (int mt = 0; mt < 2; mt++)
        aoff[mt] = swz((wm * 32 + mt * 16 + lrow) * 128 + lk * 16);
#pragma unroll
    for (int nb = 0; nb < 4; nb++)
        boff[nb] = swz((wn * 64 + nb * 16 + lrow) * 128 + lk * 16);

    float acc[2][8][4];
#pragma unroll
    for (int mt = 0; mt < 2; mt++)
#pragma unroll
        for (int nt = 0; nt < 8; nt++)
#pragma unroll
            for (int j = 0; j < 4; j++) acc[mt][nt][j] = 0.f;

    load_stage(0);
    load_stage(1);

    for (int c = 0; c < 16; c++) {
        if (c < 15) cp_wait<1>(); else cp_wait<0>();
        __syncthreads();
        if (c + 2 < 16) load_stage(c + 2);

        uint32_t stA = sbase + (c % 3) * STAGE_BYTES;
        uint32_t stB = stA + STAGE_A;

        uint32_t af[2][2][4];
        uint32_t qf[2][4][4];
        ldsm4(af[0][0][0], af[0][0][1], af[0][0][2], af[0][0][3], stA + aoff[0]);
        ldsm4(af[0][1][0], af[0][1][1], af[0][1][2], af[0][1][3], stA + aoff[1]);
#pragma unroll
        for (int nb = 0; nb < 4; nb++)
            ldsm4(qf[0][nb][0], qf[0][nb][1], qf[0][nb][2], qf[0][nb][3],
                  stB + boff[nb]);
#pragma unroll
        for (int ks = 0; ks < 4; ks++) {
            const int cur = ks & 1, nxt = cur ^ 1;
            if (ks < 3) {
                const uint32_t kx = (ks + 1) * 32;
                ldsm4(af[nxt][0][0], af[nxt][0][1], af[nxt][0][2], af[nxt][0][3],
                      stA + (aoff[0] ^ kx));
                ldsm4(af[nxt][1][0], af[nxt][1][1], af[nxt][1][2], af[nxt][1][3],
                      stA + (aoff[1] ^ kx));
#pragma unroll
                for (int nb = 0; nb < 4; nb++)
                    ldsm4(qf[nxt][nb][0], qf[nxt][nb][1], qf[nxt][nb][2],
                          qf[nxt][nb][3], stB + (boff[nb] ^ kx));
            }
#pragma unroll
            for (int nb = 0; nb < 4; nb++) {
#pragma unroll
                for (int mt = 0; mt < 2; mt++) {
                    mma16816(acc[mt][2 * nb + 0], af[cur][mt], qf[cur][nb][0],
                             qf[cur][nb][2]);
                    mma16816(acc[mt][2 * nb + 1], af[cur][mt], qf[cur][nb][1],
                             qf[cur][nb][3]);
                }
            }
        }
    }

    // -------- epilogue (exact R10 form — do not restructure) --------
    const float* lab = la + (size_t)b * Tz;
    float lm[4], l0[4], lp[4];
#pragma unroll
    for (int i = 0; i < 4; i++) {
        int r = 32 * wm + 16 * (i >> 1) + g + 8 * (i & 1);
        int t = tt0 + r;
        l0[i] = lab[t];
        lm[i] = (t > 0) ? lab[t - 1] : 0.f;
        lp[i] = (t < Tz - 1) ? lab[t + 1] : 0.f;
    }
    float rsum[4] = {0.f, 0.f, 0.f, 0.f};
#pragma unroll
    for (int mt = 0; mt < 2; mt++) {
#pragma unroll
        for (int nt = 0; nt < 8; nt++) {
#pragma unroll
            for (int j = 0; j < 4; j++) {
                int ridx = (mt << 1) | (j >> 1);
                int col = 64 * wn + 8 * nt + 2 * t4 + (j & 1);
                int a = (nchunk << 7) + col;
                float x = acc[mt][nt][j] + g_qpb[(b << 9) + a] +
                          g_cu0[a] * lm[ridx] + g_cu1[a] * l0[ridx] +
                          g_cu2[a] * lp[ridx];
                rsum[ridx] += fcw[a] * tanh_fast(x);
            }
        }
    }
    __syncthreads();
    float* scoreSm = reinterpret_cast<float*>(smem + OFF_SCORE);
#pragma unroll
    for (int i = 0; i < 4; i++) {
        float v = rsum[i];
        v += __shfl_xor_sync(0xffffffffu, v, 1);
        v += __shfl_xor_sync(0xffffffffu, v, 2);
        if (t4 == 0) {
            int r = 32 * wm + 16 * (i >> 1) + g + 8 * (i & 1);
            scoreSm[r * 2 + wn] = v;
        }
    }
    __syncthreads();
    if (tid < 128) {
        g_ps[((size_t)(mtile * 4 + nchunk)) * 128 + tid] =
            scoreSm[tid * 2 + 0] + scoreSm[tid * 2 + 1];
    }
}

// ---------------- sigmoid + normalize (deterministic) ----------------
__global__ void k_score(float* align_out) {
    int b = blockIdx.x, tid = threadIdx.x;
    __shared__ float red[256];
    float lsum = 0.f;
    for (int i = tid; i < Tz; i += 256) {
        int mtile = (b << 5) + (i >> 7);
        int r = i & 127;
        const float* p = g_ps + (size_t)mtile * 512 + r;
        float sraw = p[0] + p[128] + p[256] + p[384];
        float s = 1.f / (1.f + expf(-sraw));
        g_sN[(b << 12) + i] = s;
        lsum += s;
    }
    red[tid] = lsum;
    __syncthreads();
#pragma unroll
    for (int o = 128; o; o >>= 1) {
        if (tid < o) red[tid] += red[tid + o];
        __syncthreads();
    }
    float inv = 1.f / red[0];
    for (int i = tid; i < Tz; i += 256) {
        float v = g_sN[(b << 12) + i] * inv;
        g_sN[(b << 12) + i] = v;
        if (align_out) align_out[(size_t)(b << 12) + i] = v;
    }
}

// ---------------- context (fp32 value — bf16 here costs 1.6e-3 rel err) ---
__global__ void k_ctx(const float* __restrict__ value) {
    int tc = blockIdx.x, b = blockIdx.y, tid = threadIdx.x;
    const float4* vp =
        reinterpret_cast<const float4*>(value + ((size_t)b * Tz + tc * 128) * ENCz) + tid;
    const float* sp = g_sN + (b << 12) + (tc << 7);
    float4 acc = {0.f, 0.f, 0.f, 0.f};
#pragma unroll 4
    for (int t = 0; t < 128; t++) {
        float w = sp[t];
        float4 v = vp[(size_t)t * 256];
        acc.x += w * v.x;
        acc.y += w * v.y;
        acc.z += w * v.z;
        acc.w += w * v.w;
    }
    reinterpret_cast<float4*>(g_pctx + ((size_t)(b * 32 + tc) << 10))[tid] = acc;
}

__global__ void k_red(float* __restrict__ ctx_out) {
    int idx = blockIdx.x * 256 + threadIdx.x;
    int b = idx >> 10, e = idx & 1023;
    float s = 0.f;
#pragma unroll 8
    for (int tc = 0; tc < 32; tc++) s += g_pctx[((size_t)(b * 32 + tc) << 10) + e];
    ctx_out[idx] = s;
}

// ---------------- launch: fork-join overlap (R15 structure) ----------------
// Stream/events created ONCE on the first (non-captured) correctness call so
// the capture call performs no allocation (R16's guard failure was per-call
// priority-stream creation allocating 2 MB during capture).
extern "C" void kernel_launch(void* const* d_in, const int* in_sizes, int n_in,
                              void* d_out, int out_size) {
    const float* query  = (const float*)d_in[0];
    const float* value  = (const float*)d_in[1];
    const float* la     = (const float*)d_in[2];
    const float* conv_w = (const float*)d_in[3];
    const float* conv_b = (const float*)d_in[4];
    const float* WQ     = (const float*)d_in[5];
    const float* WV     = (const float*)d_in[6];
    const float* WU     = (const float*)d_in[7];
    const float* bias   = (const float*)d_in[8];
    const float* fcw    = (const float*)d_in[9];
    (void)in_sizes; (void)n_in;

    float* out = (float*)d_out;
    float* ctx_out = nullptr;
    float* align_out = nullptr;
    const int CTX_N = Bz * ENCz;
    const int ALN_N = Bz * Tz;
    if (out_size >= CTX_N + ALN_N) {
        ctx_out = out;
        align_out = out + CTX_N;
    } else if (out_size == ALN_N) {
        align_out = out;
    } else {
        ctx_out = out;
    }

    cudaFuncSetAttribute(k_gemm, cudaFuncAttributeMaxDynamicSharedMemorySize, SMEM_TOTAL);

    // one-time stream/event creation (first call = correctness run, uncaptured)
    static cudaStream_t s2 = nullptr;
    static cudaEvent_t ev[4], evDone;
    static bool forked = false;
    static bool tried = false;
    if (!tried) {
        tried = true;
        forked = (cudaStreamCreateWithFlags(&s2, cudaStreamNonBlocking) == cudaSuccess);
        for (int i = 0; i < 4 && forked; i++)
            forked = (cudaEventCreateWithFlags(&ev[i], cudaEventDisableTiming) == cudaSuccess);
        if (forked)
            forked = (cudaEventCreateWithFlags(&evDone, cudaEventDisableTiming) == cudaSuccess);
    }

    k_qpb_cu<<<2049, 256>>>(query, WQ, bias, WU, conv_w, conv_b);
    k_prep_wv<<<512, 256>>>((const float4*)WV);

    if (forked) {
        for (int i = 0; i < 4; i++) {
            k_prep_val<<<16384, 256>>>((const float4*)value, (size_t)i * 4194304);
            cudaEventRecord(ev[i], 0);
            cudaStreamWaitEvent(s2, ev[i], 0);
            k_gemm<<<dim3(4, 256), 256, SMEM_TOTAL, s2>>>(la, fcw, i * 256);
        }
        cudaEventRecord(evDone, s2);
        cudaStreamWaitEvent((cudaStream_t)0, evDone, 0);
    } else {
        for (int i = 0; i < 4; i++)
            k_prep_val<<<16384, 256>>>((const float4*)value, (size_t)i * 4194304);
        k_gemm<<<dim3(4, 1024), 256, SMEM_TOTAL>>>(la, fcw, 0);
    }

    k_score<<<32, 256>>>(align_out);
    if (ctx_out) {
        k_ctx<<<dim3(32, 32), 256>>>(value);
        k_red<<<128, 256>>>(ctx_out);
    }
}